// round 14
// baseline (speedup 1.0000x reference)
#include <cuda_runtime.h>
#include <cuda_bf16.h>
#include <cstdint>

#define HIDN 128
#define MAXN 100001
#define MAXE 1600000

// ---------------- scratch (no allocations allowed) ----------------
__device__ float g_h [100000*HIDN];
__device__ float g_h1[100000*HIDN];
__device__ float g_m [100000*HIDN];
__device__ float g_t [100000*HIDN];
__device__ int   g_deg[MAXN];
__device__ int   g_off[MAXN];
__device__ int   g_cur[MAXN];
__device__ int   g_csrc[MAXE];
__device__ int   g_bsums[256];

// ---------------- split + pack helpers ----------------
__device__ __forceinline__ uint32_t pack_hi2(float x, float y){
    return (__float_as_uint(x) >> 16) | (__float_as_uint(y) & 0xFFFF0000u);
}
__device__ __forceinline__ uint32_t pack_lo2(float x, float y){
    float rx = x - __uint_as_float(__float_as_uint(x) & 0xFFFF0000u);
    float ry = y - __uint_as_float(__float_as_uint(y) & 0xFFFF0000u);
    uint32_t lx = (uint32_t)__bfloat16_as_ushort(__float2bfloat16(rx));
    uint32_t ly = (uint32_t)__bfloat16_as_ushort(__float2bfloat16(ry));
    return lx | (ly << 16);
}

// D += A(16x16 bf16) @ B(16x8 bf16), fp32 acc — baseline PTX, HMMA on sm_103
__device__ __forceinline__ void mma16816(float* d, uint32_t a0, uint32_t a1, uint32_t a2, uint32_t a3,
                                         uint32_t b0, uint32_t b1){
    asm volatile(
        "mma.sync.aligned.m16n8k16.row.col.f32.bf16.bf16.f32 "
        "{%0,%1,%2,%3}, {%4,%5,%6,%7}, {%8,%9}, {%0,%1,%2,%3};"
        : "+f"(d[0]), "+f"(d[1]), "+f"(d[2]), "+f"(d[3])
        : "r"(a0), "r"(a1), "r"(a2), "r"(a3), "r"(b0), "r"(b1));
}

// ---------------- CSR build ----------------
__global__ void zero_deg(int n){
    int i = blockIdx.x*blockDim.x + threadIdx.x;
    if (i < n) g_deg[i] = 0;
}
__global__ void count_deg(const int* __restrict__ dstv, int E){
    for (int e = blockIdx.x*blockDim.x + threadIdx.x; e < E; e += gridDim.x*blockDim.x)
        atomicAdd(&g_deg[dstv[e]], 1);
}
__global__ void scan_blocks(int n){
    __shared__ int s[1024];
    int t = threadIdx.x;
    int g = blockIdx.x*1024 + t;
    int v = (g < n) ? g_deg[g] : 0;
    s[t] = v; __syncthreads();
    #pragma unroll
    for (int d = 1; d < 1024; d <<= 1){
        int x = (t >= d) ? s[t-d] : 0;
        __syncthreads();
        s[t] += x;
        __syncthreads();
    }
    if (g < n) g_off[g] = s[t] - v;
    if (t == 1023) g_bsums[blockIdx.x] = s[1023];
}
__global__ void scan_bsums(int nb, int n, int total){
    __shared__ int s[256];
    int t = threadIdx.x;
    int v = (t < nb) ? g_bsums[t] : 0;
    s[t] = v; __syncthreads();
    #pragma unroll
    for (int d = 1; d < 256; d <<= 1){
        int x = (t >= d) ? s[t-d] : 0;
        __syncthreads();
        s[t] += x;
        __syncthreads();
    }
    if (t < nb) g_bsums[t] = s[t] - v;
    if (t == 0) g_off[n] = total;
}
__global__ void add_bsums(int n){
    int g = blockIdx.x*1024 + threadIdx.x;
    if (g < n){
        int o = g_off[g] + g_bsums[blockIdx.x];
        g_off[g] = o;
        g_cur[g] = o;
    }
}
__global__ void fill_csr(const int* __restrict__ srcv, const int* __restrict__ dstv, int E){
    for (int e = blockIdx.x*blockDim.x + threadIdx.x; e < E; e += gridDim.x*blockDim.x){
        int d = dstv[e];
        int p = atomicAdd(&g_cur[d], 1);
        g_csrc[p] = srcv[e];
    }
}

// ---------------- mean aggregation: one warp per dst node ----------------
__global__ void agg_mean(const float* __restrict__ hin, float* __restrict__ mout, int n){
    int w    = (blockIdx.x*blockDim.x + threadIdx.x) >> 5;
    int lane = threadIdx.x & 31;
    if (w >= n) return;
    int beg = g_off[w], end = g_off[w+1];
    const float* base = hin + lane*4;
    float4 acc = make_float4(0.f, 0.f, 0.f, 0.f);
    int j = beg;
    for (; j + 16 <= end; j += 16){
        float4 v[16];
        #pragma unroll
        for (int t = 0; t < 16; t++){
            int s = g_csrc[j+t];
            v[t] = *(const float4*)(base + (size_t)s*HIDN);
        }
        #pragma unroll
        for (int t = 0; t < 16; t++){
            acc.x += v[t].x; acc.y += v[t].y; acc.z += v[t].z; acc.w += v[t].w;
        }
    }
    for (; j + 4 <= end; j += 4){
        float4 v[4];
        #pragma unroll
        for (int t = 0; t < 4; t++){
            int s = g_csrc[j+t];
            v[t] = *(const float4*)(base + (size_t)s*HIDN);
        }
        #pragma unroll
        for (int t = 0; t < 4; t++){
            acc.x += v[t].x; acc.y += v[t].y; acc.z += v[t].z; acc.w += v[t].w;
        }
    }
    for (; j < end; ++j){
        int s = g_csrc[j];
        float4 v = *(const float4*)(base + (size_t)s*HIDN);
        acc.x += v.x; acc.y += v.y; acc.z += v.z; acc.w += v.w;
    }
    int d = end - beg;
    float inv = 1.0f / (float)(d > 0 ? d : 1);
    float4 r = make_float4(acc.x*inv, acc.y*inv, acc.z*inv, acc.w*inv);
    *(float4*)(mout + (size_t)w*HIDN + lane*4) = r;
}

// ================= mma.sync GEMM (A direct-to-registers, no A smem) =================
// EPI modes: 0 = raw store (Wr pass: C = A@W)
//            1 = relu(acc + bias)           (encoders)
//            2 = relu(acc + Tin + bias)     (SAGE layer 1 Wl pass)
//            3 = acc + Tin + bias           (SAGE layer 2 Wl pass)
enum { MPLAIN = 0, MPOL = 1, MCOMP = 2 };

template<int MODE>
__device__ __forceinline__ float elemA(const float* __restrict__ A,
        const float* __restrict__ e0, const float* __restrict__ e1,
        int i0v, int i1v, int r, int k)
{
    if (MODE == MPOL){
        if (k < 64) return A[(size_t)r*64 + k];
        if (k < 72) return e0[(size_t)i0v*8 + (k-64)];
        return 0.f;
    } else { // MCOMP
        if (k < 96)  return A[(size_t)r*96 + k];
        if (k < 104) return e0[(size_t)i0v*8 + (k-96)];
        if (k < 112) return e1[(size_t)i1v*8 + (k-104)];
        return 0.f;
    }
}

template<int MODE, int LD>
__device__ __forceinline__ void loadfrag(
    const float* __restrict__ A, const float* __restrict__ e0, const float* __restrict__ e1,
    int i00, int i01, int i10, int i11,
    int r0, int r1, int nrows, int k0,
    uint4& ah, uint4& al)
{
    float x00=0.f,x01=0.f,x10=0.f,x11=0.f,x20=0.f,x21=0.f,x30=0.f,x31=0.f;
    if (MODE == MPLAIN){
        if (r0 < nrows){
            float2 p = *(const float2*)(A + (size_t)r0*LD + k0);
            float2 q = *(const float2*)(A + (size_t)r0*LD + k0 + 8);
            x00=p.x; x01=p.y; x20=q.x; x21=q.y;
        }
        if (r1 < nrows){
            float2 p = *(const float2*)(A + (size_t)r1*LD + k0);
            float2 q = *(const float2*)(A + (size_t)r1*LD + k0 + 8);
            x10=p.x; x11=p.y; x30=q.x; x31=q.y;
        }
    } else {
        if (r0 < nrows){
            x00 = elemA<MODE>(A,e0,e1,i00,i01,r0,k0);
            x01 = elemA<MODE>(A,e0,e1,i00,i01,r0,k0+1);
            x20 = elemA<MODE>(A,e0,e1,i00,i01,r0,k0+8);
            x21 = elemA<MODE>(A,e0,e1,i00,i01,r0,k0+9);
        }
        if (r1 < nrows){
            x10 = elemA<MODE>(A,e0,e1,i10,i11,r1,k0);
            x11 = elemA<MODE>(A,e0,e1,i10,i11,r1,k0+1);
            x30 = elemA<MODE>(A,e0,e1,i10,i11,r1,k0+8);
            x31 = elemA<MODE>(A,e0,e1,i10,i11,r1,k0+9);
        }
    }
    ah.x = pack_hi2(x00,x01); ah.y = pack_hi2(x10,x11);
    ah.z = pack_hi2(x20,x21); ah.w = pack_hi2(x30,x31);
    al.x = pack_lo2(x00,x01); al.y = pack_lo2(x10,x11);
    al.z = pack_lo2(x20,x21); al.w = pack_lo2(x30,x31);
}

template<int MODE, int LD, int KC, int WSPB>
__device__ __forceinline__ void gpass(
    const float* __restrict__ A, const float* __restrict__ e0, const float* __restrict__ e1,
    const int* __restrict__ i0, const int* __restrict__ i1,
    const uint8_t* __restrict__ sW, int wchunk0,
    int rowbase, int nrows, int wr, int wc, int lane,
    float acc[2][8][4])
{
    int g = lane >> 2, tt = lane & 3;
    int k0l = tt*2;
    int r0[2], r1[2];
    int ia[2][2], ib[2][2];
    #pragma unroll
    for (int mt = 0; mt < 2; mt++){
        r0[mt] = rowbase + wr*32 + mt*16 + g;
        r1[mt] = r0[mt] + 8;
        ia[mt][0]=ia[mt][1]=ib[mt][0]=ib[mt][1]=0;
        if (MODE != MPLAIN){
            if (r0[mt] < nrows){ ia[mt][0] = i0[r0[mt]]; if (MODE==MCOMP) ib[mt][0] = i1[r0[mt]]; }
            if (r1[mt] < nrows){ ia[mt][1] = i0[r1[mt]]; if (MODE==MCOMP) ib[mt][1] = i1[r1[mt]]; }
        }
    }

    uint4 cah[2], cal[2];
    #pragma unroll
    for (int mt = 0; mt < 2; mt++)
        loadfrag<MODE,LD>(A,e0,e1, ia[mt][0],ib[mt][0],ia[mt][1],ib[mt][1],
                          r0[mt],r1[mt],nrows, k0l, cah[mt], cal[mt]);

    #pragma unroll 2
    for (int c = 0; c < KC; c++){
        uint4 nah[2], nal[2];
        if (c + 1 < KC){
            #pragma unroll
            for (int mt = 0; mt < 2; mt++)
                loadfrag<MODE,LD>(A,e0,e1, ia[mt][0],ib[mt][0],ia[mt][1],ib[mt][1],
                                  r0[mt],r1[mt],nrows, (c+1)*16 + k0l, nah[mt], nal[mt]);
        }
        const uint8_t* bb = sW + (((uint32_t)(wchunk0 + c)*16 + wc*8)*32 + lane)*8u;
        #pragma unroll
        for (int nt = 0; nt < 8; nt++){
            uint2 bh = *(const uint2*)(bb + nt*256);
            uint2 bl = *(const uint2*)(bb + WSPB + nt*256);
            mma16816(acc[0][nt], cah[0].x, cah[0].y, cah[0].z, cah[0].w, bh.x, bh.y);
            mma16816(acc[1][nt], cah[1].x, cah[1].y, cah[1].z, cah[1].w, bh.x, bh.y);
            mma16816(acc[0][nt], cah[0].x, cah[0].y, cah[0].z, cah[0].w, bl.x, bl.y);
            mma16816(acc[1][nt], cah[1].x, cah[1].y, cah[1].z, cah[1].w, bl.x, bl.y);
            mma16816(acc[0][nt], cal[0].x, cal[0].y, cal[0].z, cal[0].w, bh.x, bh.y);
            mma16816(acc[1][nt], cal[1].x, cal[1].y, cal[1].z, cal[1].w, bh.x, bh.y);
        }
        cah[0]=nah[0]; cah[1]=nah[1]; cal[0]=nal[0]; cal[1]=nal[1];
    }
}

template<int K1, int KC1, int MODE, int EPI>
__global__ void __launch_bounds__(256)
mgemm(const float* __restrict__ A1,
      const int* __restrict__ i0, const int* __restrict__ i1,
      const float* __restrict__ e0, const float* __restrict__ e1,
      const float* __restrict__ W1,
      const float* __restrict__ bias, const float* __restrict__ Tin,
      float* __restrict__ C, int nrows)
{
    constexpr int KCT = KC1;
    constexpr int WSP = KCT*16*32*8;     // bytes per W split (fragment-linear)

    extern __shared__ uint8_t smem[];
    float*   sBias = (float*)smem;       // 512 B
    uint8_t* sW    = smem + 512;         // 2*WSP

    int tid  = threadIdx.x;
    int w    = tid >> 5, lane = tid & 31;
    int wr   = w & 3,    wc   = w >> 2;
    int g    = lane >> 2, tg  = lane & 3;

    // ---- stage W (both splits, fragment-linear), zero-padded ----
    for (int idx = tid; idx < KCT*16*32; idx += 256){
        int l  = idx & 31;
        int t  = idx >> 5;
        int nt = t & 15;
        int c  = t >> 4;
        int gg = l >> 2, tt = l & 3;
        int n  = nt*8 + gg;
        int kg = c*16 + tt*2;
        float wv[4];
        #pragma unroll
        for (int q = 0; q < 4; q++){
            int k = kg + ((q & 1) ? 1 : 0) + ((q >> 1) ? 8 : 0);
            wv[q] = (k < K1) ? W1[(size_t)k*128 + n] : 0.f;
        }
        uint32_t slot = (uint32_t)idx * 8u;
        *(uint2*)(sW + slot)       = make_uint2(pack_hi2(wv[0],wv[1]), pack_hi2(wv[2],wv[3]));
        *(uint2*)(sW + WSP + slot) = make_uint2(pack_lo2(wv[0],wv[1]), pack_lo2(wv[2],wv[3]));
    }
    if (EPI != 0)
        for (int i = tid; i < 128; i += 256) sBias[i] = bias[i];
    __syncthreads();

    int ntiles = (nrows + 127) >> 7;
    for (int tile = blockIdx.x; tile < ntiles; tile += gridDim.x){
        int rowbase = tile << 7;
        float acc[2][8][4];
        #pragma unroll
        for (int i = 0; i < 2; i++)
            #pragma unroll
            for (int j = 0; j < 8; j++)
                #pragma unroll
                for (int q = 0; q < 4; q++) acc[i][j][q] = 0.f;

        gpass<MODE, K1, KC1, WSP>(A1, e0, e1, i0, i1, sW, 0,
                                  rowbase, nrows, wr, wc, lane, acc);

        // ---- epilogue ----
        #pragma unroll
        for (int mt = 0; mt < 2; mt++){
            int r0 = rowbase + wr*32 + mt*16 + g;
            int r1 = r0 + 8;
            #pragma unroll
            for (int nt = 0; nt < 8; nt++){
                int col = wc*64 + nt*8 + tg*2;
                float c0 = acc[mt][nt][0], c1 = acc[mt][nt][1];
                float c2 = acc[mt][nt][2], c3 = acc[mt][nt][3];
                if (EPI >= 2){
                    if (r0 < nrows){
                        float2 t0 = *(const float2*)(Tin + (size_t)r0*HIDN + col);
                        c0 += t0.x; c1 += t0.y;
                    }
                    if (r1 < nrows){
                        float2 t1 = *(const float2*)(Tin + (size_t)r1*HIDN + col);
                        c2 += t1.x; c3 += t1.y;
                    }
                }
                if (EPI != 0){
                    float b0 = sBias[col], b1 = sBias[col+1];
                    c0 += b0; c1 += b1; c2 += b0; c3 += b1;
                }
                if (EPI == 1 || EPI == 2){
                    c0 = fmaxf(c0,0.f); c1 = fmaxf(c1,0.f);
                    c2 = fmaxf(c2,0.f); c3 = fmaxf(c3,0.f);
                }
                if (r0 < nrows) *(float2*)(C + (size_t)r0*HIDN + col) = make_float2(c0,c1);
                if (r1 < nrows) *(float2*)(C + (size_t)r1*HIDN + col) = make_float2(c2,c3);
            }
        }
    }
}

// ---------------- launch ----------------
extern "C" void kernel_launch(void* const* d_in, const int* in_sizes, int n_in,
                              void* d_out, int out_size){
    const float* x_pol  = (const float*)d_in[0];
    const int*   psidx  = (const int*)  d_in[1];
    const float* x_comp = (const float*)d_in[2];
    const int*   csct   = (const int*)  d_in[3];
    const int*   cind   = (const int*)  d_in[4];
    const int*   eidx   = (const int*)  d_in[5];
    const float* semb   = (const float*)d_in[6];
    const float* scemb  = (const float*)d_in[7];
    const float* iemb   = (const float*)d_in[8];
    const float* W_pol  = (const float*)d_in[9];
    const float* b_pol  = (const float*)d_in[10];
    const float* W_comp = (const float*)d_in[11];
    const float* b_comp = (const float*)d_in[12];
    const float* Wl1    = (const float*)d_in[13];
    const float* bl1    = (const float*)d_in[14];
    const float* Wr1    = (const float*)d_in[15];
    const float* Wl2    = (const float*)d_in[16];
    const float* bl2    = (const float*)d_in[17];
    const float* Wr2    = (const float*)d_in[18];
    float* out = (float*)d_out;

    int NP = in_sizes[0]/64;
    int NC = in_sizes[2]/96;
    int E  = in_sizes[5]/2;
    int N  = NP + NC;
    const int* srcv = eidx;
    const int* dstv = eidx + E;

    float *hP, *h1P, *mP, *tP;
    cudaGetSymbolAddress((void**)&hP,  g_h);
    cudaGetSymbolAddress((void**)&h1P, g_h1);
    cudaGetSymbolAddress((void**)&mP,  g_m);
    cudaGetSymbolAddress((void**)&tP,  g_t);

    const int SM_POL  = 512 + 2*(5*16*32*8);    //  41,472
    const int SM_COMP = 512 + 2*(7*16*32*8);    //  57,856
    const int SM_SAGE = 512 + 2*(8*16*32*8);    //  66,048
    cudaFuncSetAttribute(mgemm< 72, 5, MPOL,  1>, cudaFuncAttributeMaxDynamicSharedMemorySize, SM_POL);
    cudaFuncSetAttribute(mgemm<112, 7, MCOMP, 1>, cudaFuncAttributeMaxDynamicSharedMemorySize, SM_COMP);
    cudaFuncSetAttribute(mgemm<128, 8, MPLAIN,0>, cudaFuncAttributeMaxDynamicSharedMemorySize, SM_SAGE);
    cudaFuncSetAttribute(mgemm<128, 8, MPLAIN,2>, cudaFuncAttributeMaxDynamicSharedMemorySize, SM_SAGE);
    cudaFuncSetAttribute(mgemm<128, 8, MPLAIN,3>, cudaFuncAttributeMaxDynamicSharedMemorySize, SM_SAGE);

    static cudaStream_t s2 = nullptr;
    static cudaEvent_t  ev_fork = nullptr, ev_h = nullptr, ev_m1 = nullptr,
                        ev_h1 = nullptr, ev_m2 = nullptr;
    if (!s2){
        cudaStreamCreateWithFlags(&s2, cudaStreamNonBlocking);
        cudaEventCreateWithFlags(&ev_fork, cudaEventDisableTiming);
        cudaEventCreateWithFlags(&ev_h,    cudaEventDisableTiming);
        cudaEventCreateWithFlags(&ev_m1,   cudaEventDisableTiming);
        cudaEventCreateWithFlags(&ev_h1,   cudaEventDisableTiming);
        cudaEventCreateWithFlags(&ev_m2,   cudaEventDisableTiming);
    }

    cudaEventRecord(ev_fork, 0);
    cudaStreamWaitEvent(s2, ev_fork, 0);

    // ---- side stream: CSR build (independent of encoders) ----
    int NB = (N + 1023) / 1024;
    zero_deg   <<<NB, 1024, 0, s2>>>(N);
    count_deg  <<<2048, 256, 0, s2>>>(dstv, E);
    scan_blocks<<<NB, 1024, 0, s2>>>(N);
    scan_bsums <<<1, 256,   0, s2>>>(NB, N, E);
    add_bsums  <<<NB, 1024, 0, s2>>>(N);
    fill_csr   <<<2048, 256, 0, s2>>>(srcv, dstv, E);

    // ---- main: encoders ----
    mgemm< 72, 5, MPOL, 1><<<148, 256, SM_POL>>>(
        x_pol, psidx, nullptr, semb, nullptr, W_pol, b_pol, nullptr, hP, NP);
    mgemm<112, 7, MCOMP, 1><<<296, 256, SM_COMP>>>(
        x_comp, csct, cind, scemb, iemb, W_comp, b_comp, nullptr,
        hP + (size_t)NP*HIDN, NC);
    cudaEventRecord(ev_h, 0);

    // ---- layer 1: agg (side) || t = h@Wr1 (main) ----
    cudaStreamWaitEvent(s2, ev_h, 0);
    agg_mean<<<(N + 7)/8, 256, 0, s2>>>(hP, mP, N);
    cudaEventRecord(ev_m1, s2);

    mgemm<128, 8, MPLAIN, 0><<<296, 256, SM_SAGE>>>(
        hP, nullptr, nullptr, nullptr, nullptr, Wr1, nullptr, nullptr, tP, N);

    cudaStreamWaitEvent(0, ev_m1, 0);
    mgemm<128, 8, MPLAIN, 2><<<296, 256, SM_SAGE>>>(
        mP, nullptr, nullptr, nullptr, nullptr, Wl1, bl1, tP, h1P, N);
    cudaEventRecord(ev_h1, 0);

    // ---- layer 2: agg (side) || t = h1@Wr2 (main) ----
    cudaStreamWaitEvent(s2, ev_h1, 0);   // also orders agg2's write of mP after Wl1's reads
    agg_mean<<<(N + 7)/8, 256, 0, s2>>>(h1P, mP, N);
    cudaEventRecord(ev_m2, s2);

    mgemm<128, 8, MPLAIN, 0><<<296, 256, SM_SAGE>>>(
        h1P, nullptr, nullptr, nullptr, nullptr, Wr2, nullptr, nullptr, tP, N);

    cudaStreamWaitEvent(0, ev_m2, 0);
    mgemm<128, 8, MPLAIN, 3><<<296, 256, SM_SAGE>>>(
        mP, nullptr, nullptr, nullptr, nullptr, Wl2, bl2, tP, out, N);
}

// round 16
// speedup vs baseline: 1.1612x; 1.1612x over previous
#include <cuda_runtime.h>
#include <cuda_bf16.h>
#include <cstdint>

#define HIDN 128
#define MAXN 100001
#define MAXE 1600000

// ---------------- scratch (no allocations allowed) ----------------
__device__ float g_h [100000*HIDN];
__device__ float g_h1[100000*HIDN];
__device__ float g_m [100000*HIDN];
__device__ int   g_deg[MAXN];
__device__ int   g_off[MAXN];
__device__ int   g_cur[MAXN];
__device__ int   g_csrc[MAXE];
__device__ int   g_bsums[256];

// ---------------- split + pack helpers ----------------
__device__ __forceinline__ uint32_t pack_hi2(float x, float y){
    return (__float_as_uint(x) >> 16) | (__float_as_uint(y) & 0xFFFF0000u);
}
__device__ __forceinline__ uint32_t pack_lo2(float x, float y){
    float rx = x - __uint_as_float(__float_as_uint(x) & 0xFFFF0000u);
    float ry = y - __uint_as_float(__float_as_uint(y) & 0xFFFF0000u);
    uint32_t lx = (uint32_t)__bfloat16_as_ushort(__float2bfloat16(rx));
    uint32_t ly = (uint32_t)__bfloat16_as_ushort(__float2bfloat16(ry));
    return lx | (ly << 16);
}

// D += A(16x16 bf16) @ B(16x8 bf16), fp32 acc — baseline PTX, HMMA on sm_103
__device__ __forceinline__ void mma16816(float* d, uint32_t a0, uint32_t a1, uint32_t a2, uint32_t a3,
                                         uint32_t b0, uint32_t b1){
    asm volatile(
        "mma.sync.aligned.m16n8k16.row.col.f32.bf16.bf16.f32 "
        "{%0,%1,%2,%3}, {%4,%5,%6,%7}, {%8,%9}, {%0,%1,%2,%3};"
        : "+f"(d[0]), "+f"(d[1]), "+f"(d[2]), "+f"(d[3])
        : "r"(a0), "r"(a1), "r"(a2), "r"(a3), "r"(b0), "r"(b1));
}

// ---------------- CSR build ----------------
__global__ void zero_deg(int n){
    int i = blockIdx.x*blockDim.x + threadIdx.x;
    if (i < n) g_deg[i] = 0;
}
__global__ void count_deg(const int* __restrict__ dstv, int E){
    for (int e = blockIdx.x*blockDim.x + threadIdx.x; e < E; e += gridDim.x*blockDim.x)
        atomicAdd(&g_deg[dstv[e]], 1);
}
__global__ void scan_blocks(int n){
    __shared__ int s[1024];
    int t = threadIdx.x;
    int g = blockIdx.x*1024 + t;
    int v = (g < n) ? g_deg[g] : 0;
    s[t] = v; __syncthreads();
    #pragma unroll
    for (int d = 1; d < 1024; d <<= 1){
        int x = (t >= d) ? s[t-d] : 0;
        __syncthreads();
        s[t] += x;
        __syncthreads();
    }
    if (g < n) g_off[g] = s[t] - v;
    if (t == 1023) g_bsums[blockIdx.x] = s[1023];
}
__global__ void scan_bsums(int nb, int n, int total){
    __shared__ int s[256];
    int t = threadIdx.x;
    int v = (t < nb) ? g_bsums[t] : 0;
    s[t] = v; __syncthreads();
    #pragma unroll
    for (int d = 1; d < 256; d <<= 1){
        int x = (t >= d) ? s[t-d] : 0;
        __syncthreads();
        s[t] += x;
        __syncthreads();
    }
    if (t < nb) g_bsums[t] = s[t] - v;
    if (t == 0) g_off[n] = total;
}
__global__ void add_bsums(int n){
    int g = blockIdx.x*1024 + threadIdx.x;
    if (g < n){
        int o = g_off[g] + g_bsums[blockIdx.x];
        g_off[g] = o;
        g_cur[g] = o;
    }
}
__global__ void fill_csr(const int* __restrict__ srcv, const int* __restrict__ dstv, int E){
    for (int e = blockIdx.x*blockDim.x + threadIdx.x; e < E; e += gridDim.x*blockDim.x){
        int d = dstv[e];
        int p = atomicAdd(&g_cur[d], 1);
        g_csrc[p] = srcv[e];
    }
}

// ---------------- mean aggregation: one warp per dst node ----------------
__global__ void agg_mean(const float* __restrict__ hin, float* __restrict__ mout, int n){
    int w    = (blockIdx.x*blockDim.x + threadIdx.x) >> 5;
    int lane = threadIdx.x & 31;
    if (w >= n) return;
    int beg = g_off[w], end = g_off[w+1];
    const float* base = hin + lane*4;
    float4 acc = make_float4(0.f, 0.f, 0.f, 0.f);
    int j = beg;
    for (; j + 16 <= end; j += 16){
        float4 v[16];
        #pragma unroll
        for (int t = 0; t < 16; t++){
            int s = g_csrc[j+t];
            v[t] = *(const float4*)(base + (size_t)s*HIDN);
        }
        #pragma unroll
        for (int t = 0; t < 16; t++){
            acc.x += v[t].x; acc.y += v[t].y; acc.z += v[t].z; acc.w += v[t].w;
        }
    }
    for (; j + 4 <= end; j += 4){
        float4 v[4];
        #pragma unroll
        for (int t = 0; t < 4; t++){
            int s = g_csrc[j+t];
            v[t] = *(const float4*)(base + (size_t)s*HIDN);
        }
        #pragma unroll
        for (int t = 0; t < 4; t++){
            acc.x += v[t].x; acc.y += v[t].y; acc.z += v[t].z; acc.w += v[t].w;
        }
    }
    for (; j < end; ++j){
        int s = g_csrc[j];
        float4 v = *(const float4*)(base + (size_t)s*HIDN);
        acc.x += v.x; acc.y += v.y; acc.z += v.z; acc.w += v.w;
    }
    int d = end - beg;
    float inv = 1.0f / (float)(d > 0 ? d : 1);
    float4 r = make_float4(acc.x*inv, acc.y*inv, acc.z*inv, acc.w*inv);
    *(float4*)(mout + (size_t)w*HIDN + lane*4) = r;
}

// ================= mma.sync GEMM pieces (A direct-to-registers) =================
enum { MPLAIN = 0, MPOL = 1, MCOMP = 2 };

template<int MODE>
__device__ __forceinline__ float elemA(const float* __restrict__ A,
        const float* __restrict__ e0, const float* __restrict__ e1,
        int i0v, int i1v, int r, int k)
{
    if (MODE == MPOL){
        if (k < 64) return A[(size_t)r*64 + k];
        if (k < 72) return e0[(size_t)i0v*8 + (k-64)];
        return 0.f;
    } else { // MCOMP
        if (k < 96)  return A[(size_t)r*96 + k];
        if (k < 104) return e0[(size_t)i0v*8 + (k-96)];
        if (k < 112) return e1[(size_t)i1v*8 + (k-104)];
        return 0.f;
    }
}

template<int MODE, int LD>
__device__ __forceinline__ void loadfrag(
    const float* __restrict__ A, const float* __restrict__ e0, const float* __restrict__ e1,
    int i00, int i01, int i10, int i11,
    int r0, int r1, int nrows, int k0,
    uint4& ah, uint4& al)
{
    float x00=0.f,x01=0.f,x10=0.f,x11=0.f,x20=0.f,x21=0.f,x30=0.f,x31=0.f;
    if (MODE == MPLAIN){
        if (r0 < nrows){
            float2 p = *(const float2*)(A + (size_t)r0*LD + k0);
            float2 q = *(const float2*)(A + (size_t)r0*LD + k0 + 8);
            x00=p.x; x01=p.y; x20=q.x; x21=q.y;
        }
        if (r1 < nrows){
            float2 p = *(const float2*)(A + (size_t)r1*LD + k0);
            float2 q = *(const float2*)(A + (size_t)r1*LD + k0 + 8);
            x10=p.x; x11=p.y; x30=q.x; x31=q.y;
        }
    } else {
        if (r0 < nrows){
            x00 = elemA<MODE>(A,e0,e1,i00,i01,r0,k0);
            x01 = elemA<MODE>(A,e0,e1,i00,i01,r0,k0+1);
            x20 = elemA<MODE>(A,e0,e1,i00,i01,r0,k0+8);
            x21 = elemA<MODE>(A,e0,e1,i00,i01,r0,k0+9);
        }
        if (r1 < nrows){
            x10 = elemA<MODE>(A,e0,e1,i10,i11,r1,k0);
            x11 = elemA<MODE>(A,e0,e1,i10,i11,r1,k0+1);
            x30 = elemA<MODE>(A,e0,e1,i10,i11,r1,k0+8);
            x31 = elemA<MODE>(A,e0,e1,i10,i11,r1,k0+9);
        }
    }
    ah.x = pack_hi2(x00,x01); ah.y = pack_hi2(x10,x11);
    ah.z = pack_hi2(x20,x21); ah.w = pack_hi2(x30,x31);
    al.x = pack_lo2(x00,x01); al.y = pack_lo2(x10,x11);
    al.z = pack_lo2(x20,x21); al.w = pack_lo2(x30,x31);
}

template<int MODE, int LD, int KC, int WSPB, int NTT, int NTW>
__device__ __forceinline__ void gpass(
    const float* __restrict__ A, const float* __restrict__ e0, const float* __restrict__ e1,
    const int* __restrict__ i0, const int* __restrict__ i1,
    const uint8_t* __restrict__ sW, int wchunk0,
    int rowbase, int nrows, int wr, int wc, int lane,
    float (&acc)[2][NTW][4])
{
    int g = lane >> 2, tt = lane & 3;
    int k0l = tt*2;
    int r0[2], r1[2];
    int ia[2][2], ib[2][2];
    #pragma unroll
    for (int mt = 0; mt < 2; mt++){
        r0[mt] = rowbase + wr*32 + mt*16 + g;
        r1[mt] = r0[mt] + 8;
        ia[mt][0]=ia[mt][1]=ib[mt][0]=ib[mt][1]=0;
        if (MODE != MPLAIN){
            if (r0[mt] < nrows){ ia[mt][0] = i0[r0[mt]]; if (MODE==MCOMP) ib[mt][0] = i1[r0[mt]]; }
            if (r1[mt] < nrows){ ia[mt][1] = i0[r1[mt]]; if (MODE==MCOMP) ib[mt][1] = i1[r1[mt]]; }
        }
    }

    uint4 cah[2], cal[2];
    #pragma unroll
    for (int mt = 0; mt < 2; mt++)
        loadfrag<MODE,LD>(A,e0,e1, ia[mt][0],ib[mt][0],ia[mt][1],ib[mt][1],
                          r0[mt],r1[mt],nrows, k0l, cah[mt], cal[mt]);

    #pragma unroll 2
    for (int c = 0; c < KC; c++){
        uint4 nah[2], nal[2];
        if (c + 1 < KC){
            #pragma unroll
            for (int mt = 0; mt < 2; mt++)
                loadfrag<MODE,LD>(A,e0,e1, ia[mt][0],ib[mt][0],ia[mt][1],ib[mt][1],
                                  r0[mt],r1[mt],nrows, (c+1)*16 + k0l, nah[mt], nal[mt]);
        }
        const uint8_t* bb = sW + (((uint32_t)(wchunk0 + c)*NTT + wc*NTW)*32 + lane)*8u;
        #pragma unroll
        for (int nt = 0; nt < NTW; nt++){
            uint2 bh = *(const uint2*)(bb + nt*256);
            uint2 bl = *(const uint2*)(bb + WSPB + nt*256);
            mma16816(acc[0][nt], cah[0].x, cah[0].y, cah[0].z, cah[0].w, bh.x, bh.y);
            mma16816(acc[1][nt], cah[1].x, cah[1].y, cah[1].z, cah[1].w, bh.x, bh.y);
            mma16816(acc[0][nt], cah[0].x, cah[0].y, cah[0].z, cah[0].w, bl.x, bl.y);
            mma16816(acc[1][nt], cah[1].x, cah[1].y, cah[1].z, cah[1].w, bl.x, bl.y);
            mma16816(acc[0][nt], cal[0].x, cal[0].y, cal[0].z, cal[0].w, bh.x, bh.y);
            mma16816(acc[1][nt], cal[1].x, cal[1].y, cal[1].z, cal[1].w, bh.x, bh.y);
        }
        cah[0]=nah[0]; cah[1]=nah[1]; cal[0]=nal[0]; cal[1]=nal[1];
    }
}

// ---- encoder GEMM: full 128 cols per CTA (R13-proven shape) ----
template<int K1, int KC1, int MODE>
__global__ void __launch_bounds__(256)
mgemm_enc(const float* __restrict__ A1,
          const int* __restrict__ i0, const int* __restrict__ i1,
          const float* __restrict__ e0, const float* __restrict__ e1,
          const float* __restrict__ W1,
          const float* __restrict__ bias, float* __restrict__ C, int nrows)
{
    constexpr int WSP = KC1*16*32*8;

    extern __shared__ uint8_t smem[];
    float*   sBias = (float*)smem;
    uint8_t* sW    = smem + 512;

    int tid  = threadIdx.x;
    int w    = tid >> 5, lane = tid & 31;
    int wr   = w & 3,    wc   = w >> 2;
    int g    = lane >> 2, tg  = lane & 3;

    for (int idx = tid; idx < KC1*16*32; idx += 256){
        int l  = idx & 31;
        int t  = idx >> 5;
        int nt = t & 15;
        int c  = t >> 4;
        int gg = l >> 2, tt = l & 3;
        int n  = nt*8 + gg;
        int kg = c*16 + tt*2;
        float wv[4];
        #pragma unroll
        for (int q = 0; q < 4; q++){
            int k = kg + ((q & 1) ? 1 : 0) + ((q >> 1) ? 8 : 0);
            wv[q] = (k < K1) ? W1[(size_t)k*128 + n] : 0.f;
        }
        uint32_t slot = (uint32_t)idx * 8u;
        *(uint2*)(sW + slot)       = make_uint2(pack_hi2(wv[0],wv[1]), pack_hi2(wv[2],wv[3]));
        *(uint2*)(sW + WSP + slot) = make_uint2(pack_lo2(wv[0],wv[1]), pack_lo2(wv[2],wv[3]));
    }
    for (int i = tid; i < 128; i += 256) sBias[i] = bias[i];
    __syncthreads();

    int ntiles = (nrows + 127) >> 7;
    for (int tile = blockIdx.x; tile < ntiles; tile += gridDim.x){
        int rowbase = tile << 7;
        float acc[2][8][4];
        #pragma unroll
        for (int i = 0; i < 2; i++)
            #pragma unroll
            for (int j = 0; j < 8; j++)
                #pragma unroll
                for (int q = 0; q < 4; q++) acc[i][j][q] = 0.f;

        gpass<MODE, K1, KC1, WSP, 16, 8>(A1, e0, e1, i0, i1, sW, 0,
                                         rowbase, nrows, wr, wc, lane, acc);

        #pragma unroll
        for (int mt = 0; mt < 2; mt++){
            int r0 = rowbase + wr*32 + mt*16 + g;
            int r1 = r0 + 8;
            #pragma unroll
            for (int nt = 0; nt < 8; nt++){
                int col = (wc*8 + nt)*8 + tg*2;
                float b0 = sBias[col], b1 = sBias[col+1];
                float c0 = fmaxf(acc[mt][nt][0] + b0, 0.f);
                float c1 = fmaxf(acc[mt][nt][1] + b1, 0.f);
                float c2 = fmaxf(acc[mt][nt][2] + b0, 0.f);
                float c3 = fmaxf(acc[mt][nt][3] + b1, 0.f);
                if (r0 < nrows) *(float2*)(C + (size_t)r0*HIDN + col) = make_float2(c0,c1);
                if (r1 < nrows) *(float2*)(C + (size_t)r1*HIDN + col) = make_float2(c2,c3);
            }
        }
    }
}

// ---- SAGE GEMM: column-split, 64 cols per CTA, 2 CTAs/SM ----
__global__ void __launch_bounds__(256, 2)
mgemm_sage(const float* __restrict__ A1, const float* __restrict__ A2,
           const float* __restrict__ W1, const float* __restrict__ W2,
           const float* __restrict__ bias, float* __restrict__ C,
           int nrows, int relu)
{
    const int WSP = 16*8*32*8;    // 32768 bytes per split (16 chunks x 8 n-tiles)

    extern __shared__ uint8_t smem[];
    float*   sBias = (float*)smem;
    uint8_t* sW    = smem + 512;

    int tid  = threadIdx.x;
    int w    = tid >> 5, lane = tid & 31;
    int wr   = w & 3,    wc   = w >> 2;
    int g    = lane >> 2, tg  = lane & 3;
    int half   = (int)(blockIdx.x & 1);
    int bstart = (int)(blockIdx.x >> 1);
    int bstep  = (int)(gridDim.x >> 1);

    // stage this CTA's 64 columns of [W1;W2] (16 K-chunks), both splits
    for (int idx = tid; idx < 16*8*32; idx += 256){
        int l   = idx & 31;
        int t   = idx >> 5;
        int ntl = t & 7;
        int c   = t >> 3;
        int gg  = l >> 2, tt = l & 3;
        int n   = (half*8 + ntl)*8 + gg;
        int kg  = c*16 + tt*2;
        float wv[4];
        #pragma unroll
        for (int q = 0; q < 4; q++){
            int k = kg + ((q & 1) ? 1 : 0) + ((q >> 1) ? 8 : 0);
            wv[q] = (k < 128) ? W1[(size_t)k*128 + n] : W2[(size_t)(k-128)*128 + n];
        }
        uint32_t slot = (uint32_t)idx * 8u;
        *(uint2*)(sW + slot)       = make_uint2(pack_hi2(wv[0],wv[1]), pack_hi2(wv[2],wv[3]));
        *(uint2*)(sW + WSP + slot) = make_uint2(pack_lo2(wv[0],wv[1]), pack_lo2(wv[2],wv[3]));
    }
    for (int i = tid; i < 128; i += 256) sBias[i] = bias[i];
    __syncthreads();

    int ntiles = (nrows + 127) >> 7;
    for (int tile = bstart; tile < ntiles; tile += bstep){
        int rowbase = tile << 7;
        float acc[2][4][4];
        #pragma unroll
        for (int i = 0; i < 2; i++)
            #pragma unroll
            for (int j = 0; j < 4; j++)
                #pragma unroll
                for (int q = 0; q < 4; q++) acc[i][j][q] = 0.f;

        gpass<MPLAIN, 128, 8, 16*8*32*8, 8, 4>(A1, nullptr, nullptr, nullptr, nullptr, sW, 0,
                                               rowbase, nrows, wr, wc, lane, acc);
        gpass<MPLAIN, 128, 8, 16*8*32*8, 8, 4>(A2, nullptr, nullptr, nullptr, nullptr, sW, 8,
                                               rowbase, nrows, wr, wc, lane, acc);

        #pragma unroll
        for (int mt = 0; mt < 2; mt++){
            int r0 = rowbase + wr*32 + mt*16 + g;
            int r1 = r0 + 8;
            #pragma unroll
            for (int nt = 0; nt < 4; nt++){
                int col = (half*8 + wc*4 + nt)*8 + tg*2;
                float b0 = sBias[col], b1 = sBias[col+1];
                float c0 = acc[mt][nt][0] + b0, c1 = acc[mt][nt][1] + b1;
                float c2 = acc[mt][nt][2] + b0, c3 = acc[mt][nt][3] + b1;
                if (relu){
                    c0 = fmaxf(c0,0.f); c1 = fmaxf(c1,0.f);
                    c2 = fmaxf(c2,0.f); c3 = fmaxf(c3,0.f);
                }
                if (r0 < nrows) *(float2*)(C + (size_t)r0*HIDN + col) = make_float2(c0,c1);
                if (r1 < nrows) *(float2*)(C + (size_t)r1*HIDN + col) = make_float2(c2,c3);
            }
        }
    }
}

// ---------------- launch ----------------
extern "C" void kernel_launch(void* const* d_in, const int* in_sizes, int n_in,
                              void* d_out, int out_size){
    const float* x_pol  = (const float*)d_in[0];
    const int*   psidx  = (const int*)  d_in[1];
    const float* x_comp = (const float*)d_in[2];
    const int*   csct   = (const int*)  d_in[3];
    const int*   cind   = (const int*)  d_in[4];
    const int*   eidx   = (const int*)  d_in[5];
    const float* semb   = (const float*)d_in[6];
    const float* scemb  = (const float*)d_in[7];
    const float* iemb   = (const float*)d_in[8];
    const float* W_pol  = (const float*)d_in[9];
    const float* b_pol  = (const float*)d_in[10];
    const float* W_comp = (const float*)d_in[11];
    const float* b_comp = (const float*)d_in[12];
    const float* Wl1    = (const float*)d_in[13];
    const float* bl1    = (const float*)d_in[14];
    const float* Wr1    = (const float*)d_in[15];
    const float* Wl2    = (const float*)d_in[16];
    const float* bl2    = (const float*)d_in[17];
    const float* Wr2    = (const float*)d_in[18];
    float* out = (float*)d_out;

    int NP = in_sizes[0]/64;
    int NC = in_sizes[2]/96;
    int E  = in_sizes[5]/2;
    int N  = NP + NC;
    const int* srcv = eidx;
    const int* dstv = eidx + E;

    float *hP, *h1P, *mP;
    cudaGetSymbolAddress((void**)&hP,  g_h);
    cudaGetSymbolAddress((void**)&h1P, g_h1);
    cudaGetSymbolAddress((void**)&mP,  g_m);

    const int SM_POL  = 512 + 2*( 5*16*32*8);   //  41,472
    const int SM_COMP = 512 + 2*( 7*16*32*8);   //  57,856
    const int SM_SAGE = 512 + 2*(16* 8*32*8);   //  66,048
    cudaFuncSetAttribute(mgemm_enc< 72, 5, MPOL >, cudaFuncAttributeMaxDynamicSharedMemorySize, SM_POL);
    cudaFuncSetAttribute(mgemm_enc<112, 7, MCOMP>, cudaFuncAttributeMaxDynamicSharedMemorySize, SM_COMP);
    cudaFuncSetAttribute(mgemm_sage,               cudaFuncAttributeMaxDynamicSharedMemorySize, SM_SAGE);

    static cudaStream_t s2 = nullptr;
    static cudaEvent_t  ev_fork = nullptr, ev_h = nullptr, ev_m1 = nullptr,
                        ev_h1 = nullptr, ev_m2 = nullptr;
    if (!s2){
        cudaStreamCreateWithFlags(&s2, cudaStreamNonBlocking);
        cudaEventCreateWithFlags(&ev_fork, cudaEventDisableTiming);
        cudaEventCreateWithFlags(&ev_h,    cudaEventDisableTiming);
        cudaEventCreateWithFlags(&ev_m1,   cudaEventDisableTiming);
        cudaEventCreateWithFlags(&ev_h1,   cudaEventDisableTiming);
        cudaEventCreateWithFlags(&ev_m2,   cudaEventDisableTiming);
    }

    cudaEventRecord(ev_fork, 0);
    cudaStreamWaitEvent(s2, ev_fork, 0);

    // ---- side stream s2: CSR build (concurrent with encoders) ----
    int NB = (N + 1023) / 1024;
    zero_deg   <<<NB, 1024, 0, s2>>>(N);
    count_deg  <<<2048, 256, 0, s2>>>(dstv, E);
    scan_blocks<<<NB, 1024, 0, s2>>>(N);
    scan_bsums <<<1, 256,   0, s2>>>(NB, N, E);
    add_bsums  <<<NB, 1024, 0, s2>>>(N);
    fill_csr   <<<2048, 256, 0, s2>>>(srcv, dstv, E);

    // ---- main: encoders ----
    mgemm_enc< 72, 5, MPOL ><<<148, 256, SM_POL>>>(
        x_pol, psidx, nullptr, semb, nullptr, W_pol, b_pol, hP, NP);
    mgemm_enc<112, 7, MCOMP><<<148, 256, SM_COMP>>>(
        x_comp, csct, cind, scemb, iemb, W_comp, b_comp,
        hP + (size_t)NP*HIDN, NC);
    cudaEventRecord(ev_h, 0);

    // ---- layer 1 ----
    cudaStreamWaitEvent(s2, ev_h, 0);
    agg_mean<<<(N + 7)/8, 256, 0, s2>>>(hP, mP, N);
    cudaEventRecord(ev_m1, s2);
    cudaStreamWaitEvent(0, ev_m1, 0);
    mgemm_sage<<<296, 256, SM_SAGE>>>(mP, hP, Wl1, Wr1, bl1, h1P, N, 1);
    cudaEventRecord(ev_h1, 0);

    // ---- layer 2 -> d_out ----
    cudaStreamWaitEvent(s2, ev_h1, 0);
    agg_mean<<<(N + 7)/8, 256, 0, s2>>>(h1P, mP, N);
    cudaEventRecord(ev_m2, s2);
    cudaStreamWaitEvent(0, ev_m2, 0);
    mgemm_sage<<<296, 256, SM_SAGE>>>(mP, h1P, Wl2, Wr2, bl2, out, N, 0);
}

// round 17
// speedup vs baseline: 1.1901x; 1.0249x over previous
#include <cuda_runtime.h>
#include <cuda_bf16.h>
#include <cstdint>

#define HIDN 128
#define MAXN 100001
#define MAXE 1600000

// ---------------- scratch (no allocations allowed) ----------------
__device__ float    g_h [100000*HIDN];
__device__ float    g_h1[100000*HIDN];
__device__ float    g_m [100000*HIDN];
__device__ uint32_t g_hb[100000*64];     // bf16x2-packed mirror of h / h1 (agg feed)
__device__ int   g_deg[MAXN];
__device__ int   g_off[MAXN];
__device__ int   g_cur[MAXN];
__device__ int   g_csrc[MAXE];
__device__ int   g_bsums[256];

// ---------------- split + pack helpers ----------------
__device__ __forceinline__ uint32_t pack_hi2(float x, float y){
    return (__float_as_uint(x) >> 16) | (__float_as_uint(y) & 0xFFFF0000u);
}
__device__ __forceinline__ uint32_t pack_lo2(float x, float y){
    float rx = x - __uint_as_float(__float_as_uint(x) & 0xFFFF0000u);
    float ry = y - __uint_as_float(__float_as_uint(y) & 0xFFFF0000u);
    uint32_t lx = (uint32_t)__bfloat16_as_ushort(__float2bfloat16(rx));
    uint32_t ly = (uint32_t)__bfloat16_as_ushort(__float2bfloat16(ry));
    return lx | (ly << 16);
}
// pack {lo=c0, hi=c1} as bf16x2 (round-to-nearest)
__device__ __forceinline__ uint32_t bf2_rn(float c0, float c1){
    uint32_t r;
    asm("cvt.rn.bf16x2.f32 %0, %1, %2;" : "=r"(r) : "f"(c1), "f"(c0));
    return r;
}

// D += A(16x16 bf16) @ B(16x8 bf16), fp32 acc — baseline PTX, HMMA on sm_103
__device__ __forceinline__ void mma16816(float* d, uint32_t a0, uint32_t a1, uint32_t a2, uint32_t a3,
                                         uint32_t b0, uint32_t b1){
    asm volatile(
        "mma.sync.aligned.m16n8k16.row.col.f32.bf16.bf16.f32 "
        "{%0,%1,%2,%3}, {%4,%5,%6,%7}, {%8,%9}, {%0,%1,%2,%3};"
        : "+f"(d[0]), "+f"(d[1]), "+f"(d[2]), "+f"(d[3])
        : "r"(a0), "r"(a1), "r"(a2), "r"(a3), "r"(b0), "r"(b1));
}

// ---------------- CSR build ----------------
__global__ void zero_deg(int n){
    int i = blockIdx.x*blockDim.x + threadIdx.x;
    if (i < n) g_deg[i] = 0;
}
__global__ void count_deg(const int* __restrict__ dstv, int E){
    for (int e = blockIdx.x*blockDim.x + threadIdx.x; e < E; e += gridDim.x*blockDim.x)
        atomicAdd(&g_deg[dstv[e]], 1);
}
__global__ void scan_blocks(int n){
    __shared__ int s[1024];
    int t = threadIdx.x;
    int g = blockIdx.x*1024 + t;
    int v = (g < n) ? g_deg[g] : 0;
    s[t] = v; __syncthreads();
    #pragma unroll
    for (int d = 1; d < 1024; d <<= 1){
        int x = (t >= d) ? s[t-d] : 0;
        __syncthreads();
        s[t] += x;
        __syncthreads();
    }
    if (g < n) g_off[g] = s[t] - v;
    if (t == 1023) g_bsums[blockIdx.x] = s[1023];
}
__global__ void scan_bsums(int nb, int n, int total){
    __shared__ int s[256];
    int t = threadIdx.x;
    int v = (t < nb) ? g_bsums[t] : 0;
    s[t] = v; __syncthreads();
    #pragma unroll
    for (int d = 1; d < 256; d <<= 1){
        int x = (t >= d) ? s[t-d] : 0;
        __syncthreads();
        s[t] += x;
        __syncthreads();
    }
    if (t < nb) g_bsums[t] = s[t] - v;
    if (t == 0) g_off[n] = total;
}
__global__ void add_bsums(int n){
    int g = blockIdx.x*1024 + threadIdx.x;
    if (g < n){
        int o = g_off[g] + g_bsums[blockIdx.x];
        g_off[g] = o;
        g_cur[g] = o;
    }
}
__global__ void fill_csr(const int* __restrict__ srcv, const int* __restrict__ dstv, int E){
    for (int e = blockIdx.x*blockDim.x + threadIdx.x; e < E; e += gridDim.x*blockDim.x){
        int d = dstv[e];
        int p = atomicAdd(&g_cur[d], 1);
        g_csrc[p] = srcv[e];
    }
}

// ---------------- mean aggregation over bf16-packed h: one warp per dst node ----------------
// Each lane owns 4 columns (lane*4..+3) = one uint2 (4 bf16) per src row; 256B/row coalesced.
__global__ void agg_mean_bf(const uint32_t* __restrict__ hb, float* __restrict__ mout, int n){
    int w    = (blockIdx.x*blockDim.x + threadIdx.x) >> 5;
    int lane = threadIdx.x & 31;
    if (w >= n) return;
    int beg = g_off[w], end = g_off[w+1];
    const uint2* base = (const uint2*)hb + lane;    // 8B per lane within the 256B row
    float4 acc = make_float4(0.f, 0.f, 0.f, 0.f);
    int j = beg;
    for (; j + 16 <= end; j += 16){
        uint2 v[16];
        #pragma unroll
        for (int t = 0; t < 16; t++){
            int s = g_csrc[j+t];
            v[t] = base[(size_t)s*32];
        }
        #pragma unroll
        for (int t = 0; t < 16; t++){
            acc.x += __uint_as_float(v[t].x << 16);
            acc.y += __uint_as_float(v[t].x & 0xFFFF0000u);
            acc.z += __uint_as_float(v[t].y << 16);
            acc.w += __uint_as_float(v[t].y & 0xFFFF0000u);
        }
    }
    for (; j + 4 <= end; j += 4){
        uint2 v[4];
        #pragma unroll
        for (int t = 0; t < 4; t++){
            int s = g_csrc[j+t];
            v[t] = base[(size_t)s*32];
        }
        #pragma unroll
        for (int t = 0; t < 4; t++){
            acc.x += __uint_as_float(v[t].x << 16);
            acc.y += __uint_as_float(v[t].x & 0xFFFF0000u);
            acc.z += __uint_as_float(v[t].y << 16);
            acc.w += __uint_as_float(v[t].y & 0xFFFF0000u);
        }
    }
    for (; j < end; ++j){
        uint2 v = base[(size_t)g_csrc[j]*32];
        acc.x += __uint_as_float(v.x << 16);
        acc.y += __uint_as_float(v.x & 0xFFFF0000u);
        acc.z += __uint_as_float(v.y << 16);
        acc.w += __uint_as_float(v.y & 0xFFFF0000u);
    }
    int d = end - beg;
    float inv = 1.0f / (float)(d > 0 ? d : 1);
    float4 r = make_float4(acc.x*inv, acc.y*inv, acc.z*inv, acc.w*inv);
    *(float4*)(mout + (size_t)w*HIDN + lane*4) = r;
}

// ================= mma.sync GEMM pieces (A direct-to-registers) =================
enum { MPLAIN = 0, MPOL = 1, MCOMP = 2 };

template<int MODE>
__device__ __forceinline__ float elemA(const float* __restrict__ A,
        const float* __restrict__ e0, const float* __restrict__ e1,
        int i0v, int i1v, int r, int k)
{
    if (MODE == MPOL){
        if (k < 64) return A[(size_t)r*64 + k];
        if (k < 72) return e0[(size_t)i0v*8 + (k-64)];
        return 0.f;
    } else { // MCOMP
        if (k < 96)  return A[(size_t)r*96 + k];
        if (k < 104) return e0[(size_t)i0v*8 + (k-96)];
        if (k < 112) return e1[(size_t)i1v*8 + (k-104)];
        return 0.f;
    }
}

template<int MODE, int LD>
__device__ __forceinline__ void loadfrag(
    const float* __restrict__ A, const float* __restrict__ e0, const float* __restrict__ e1,
    int i00, int i01, int i10, int i11,
    int r0, int r1, int nrows, int k0,
    uint4& ah, uint4& al)
{
    float x00=0.f,x01=0.f,x10=0.f,x11=0.f,x20=0.f,x21=0.f,x30=0.f,x31=0.f;
    if (MODE == MPLAIN){
        if (r0 < nrows){
            float2 p = *(const float2*)(A + (size_t)r0*LD + k0);
            float2 q = *(const float2*)(A + (size_t)r0*LD + k0 + 8);
            x00=p.x; x01=p.y; x20=q.x; x21=q.y;
        }
        if (r1 < nrows){
            float2 p = *(const float2*)(A + (size_t)r1*LD + k0);
            float2 q = *(const float2*)(A + (size_t)r1*LD + k0 + 8);
            x10=p.x; x11=p.y; x30=q.x; x31=q.y;
        }
    } else {
        if (r0 < nrows){
            x00 = elemA<MODE>(A,e0,e1,i00,i01,r0,k0);
            x01 = elemA<MODE>(A,e0,e1,i00,i01,r0,k0+1);
            x20 = elemA<MODE>(A,e0,e1,i00,i01,r0,k0+8);
            x21 = elemA<MODE>(A,e0,e1,i00,i01,r0,k0+9);
        }
        if (r1 < nrows){
            x10 = elemA<MODE>(A,e0,e1,i10,i11,r1,k0);
            x11 = elemA<MODE>(A,e0,e1,i10,i11,r1,k0+1);
            x30 = elemA<MODE>(A,e0,e1,i10,i11,r1,k0+8);
            x31 = elemA<MODE>(A,e0,e1,i10,i11,r1,k0+9);
        }
    }
    ah.x = pack_hi2(x00,x01); ah.y = pack_hi2(x10,x11);
    ah.z = pack_hi2(x20,x21); ah.w = pack_hi2(x30,x31);
    al.x = pack_lo2(x00,x01); al.y = pack_lo2(x10,x11);
    al.z = pack_lo2(x20,x21); al.w = pack_lo2(x30,x31);
}

template<int MODE, int LD, int KC, int WSPB, int NTT, int NTW>
__device__ __forceinline__ void gpass(
    const float* __restrict__ A, const float* __restrict__ e0, const float* __restrict__ e1,
    const int* __restrict__ i0, const int* __restrict__ i1,
    const uint8_t* __restrict__ sW, int wchunk0,
    int rowbase, int nrows, int wr, int wc, int lane,
    float (&acc)[2][NTW][4])
{
    int g = lane >> 2, tt = lane & 3;
    int k0l = tt*2;
    int r0[2], r1[2];
    int ia[2][2], ib[2][2];
    #pragma unroll
    for (int mt = 0; mt < 2; mt++){
        r0[mt] = rowbase + wr*32 + mt*16 + g;
        r1[mt] = r0[mt] + 8;
        ia[mt][0]=ia[mt][1]=ib[mt][0]=ib[mt][1]=0;
        if (MODE != MPLAIN){
            if (r0[mt] < nrows){ ia[mt][0] = i0[r0[mt]]; if (MODE==MCOMP) ib[mt][0] = i1[r0[mt]]; }
            if (r1[mt] < nrows){ ia[mt][1] = i0[r1[mt]]; if (MODE==MCOMP) ib[mt][1] = i1[r1[mt]]; }
        }
    }

    uint4 cah[2], cal[2];
    #pragma unroll
    for (int mt = 0; mt < 2; mt++)
        loadfrag<MODE,LD>(A,e0,e1, ia[mt][0],ib[mt][0],ia[mt][1],ib[mt][1],
                          r0[mt],r1[mt],nrows, k0l, cah[mt], cal[mt]);

    #pragma unroll 2
    for (int c = 0; c < KC; c++){
        uint4 nah[2], nal[2];
        if (c + 1 < KC){
            #pragma unroll
            for (int mt = 0; mt < 2; mt++)
                loadfrag<MODE,LD>(A,e0,e1, ia[mt][0],ib[mt][0],ia[mt][1],ib[mt][1],
                                  r0[mt],r1[mt],nrows, (c+1)*16 + k0l, nah[mt], nal[mt]);
        }
        const uint8_t* bb = sW + (((uint32_t)(wchunk0 + c)*NTT + wc*NTW)*32 + lane)*8u;
        #pragma unroll
        for (int nt = 0; nt < NTW; nt++){
            uint2 bh = *(const uint2*)(bb + nt*256);
            uint2 bl = *(const uint2*)(bb + WSPB + nt*256);
            mma16816(acc[0][nt], cah[0].x, cah[0].y, cah[0].z, cah[0].w, bh.x, bh.y);
            mma16816(acc[1][nt], cah[1].x, cah[1].y, cah[1].z, cah[1].w, bh.x, bh.y);
            mma16816(acc[0][nt], cah[0].x, cah[0].y, cah[0].z, cah[0].w, bl.x, bl.y);
            mma16816(acc[1][nt], cah[1].x, cah[1].y, cah[1].z, cah[1].w, bl.x, bl.y);
            mma16816(acc[0][nt], cal[0].x, cal[0].y, cal[0].z, cal[0].w, bh.x, bh.y);
            mma16816(acc[1][nt], cal[1].x, cal[1].y, cal[1].z, cal[1].w, bh.x, bh.y);
        }
        cah[0]=nah[0]; cah[1]=nah[1]; cal[0]=nal[0]; cal[1]=nal[1];
    }
}

// ---- encoder GEMM: full 128 cols per CTA; also emits bf16 mirror for agg ----
template<int K1, int KC1, int MODE>
__global__ void __launch_bounds__(256)
mgemm_enc(const float* __restrict__ A1,
          const int* __restrict__ i0, const int* __restrict__ i1,
          const float* __restrict__ e0, const float* __restrict__ e1,
          const float* __restrict__ W1,
          const float* __restrict__ bias, float* __restrict__ C,
          uint32_t* __restrict__ Cb, int nrows)
{
    constexpr int WSP = KC1*16*32*8;

    extern __shared__ uint8_t smem[];
    float*   sBias = (float*)smem;
    uint8_t* sW    = smem + 512;

    int tid  = threadIdx.x;
    int w    = tid >> 5, lane = tid & 31;
    int wr   = w & 3,    wc   = w >> 2;
    int g    = lane >> 2, tg  = lane & 3;

    for (int idx = tid; idx < KC1*16*32; idx += 256){
        int l  = idx & 31;
        int t  = idx >> 5;
        int nt = t & 15;
        int c  = t >> 4;
        int gg = l >> 2, tt = l & 3;
        int n  = nt*8 + gg;
        int kg = c*16 + tt*2;
        float wv[4];
        #pragma unroll
        for (int q = 0; q < 4; q++){
            int k = kg + ((q & 1) ? 1 : 0) + ((q >> 1) ? 8 : 0);
            wv[q] = (k < K1) ? W1[(size_t)k*128 + n] : 0.f;
        }
        uint32_t slot = (uint32_t)idx * 8u;
        *(uint2*)(sW + slot)       = make_uint2(pack_hi2(wv[0],wv[1]), pack_hi2(wv[2],wv[3]));
        *(uint2*)(sW + WSP + slot) = make_uint2(pack_lo2(wv[0],wv[1]), pack_lo2(wv[2],wv[3]));
    }
    for (int i = tid; i < 128; i += 256) sBias[i] = bias[i];
    __syncthreads();

    int ntiles = (nrows + 127) >> 7;
    for (int tile = blockIdx.x; tile < ntiles; tile += gridDim.x){
        int rowbase = tile << 7;
        float acc[2][8][4];
        #pragma unroll
        for (int i = 0; i < 2; i++)
            #pragma unroll
            for (int j = 0; j < 8; j++)
                #pragma unroll
                for (int q = 0; q < 4; q++) acc[i][j][q] = 0.f;

        gpass<MODE, K1, KC1, WSP, 16, 8>(A1, e0, e1, i0, i1, sW, 0,
                                         rowbase, nrows, wr, wc, lane, acc);

        #pragma unroll
        for (int mt = 0; mt < 2; mt++){
            int r0 = rowbase + wr*32 + mt*16 + g;
            int r1 = r0 + 8;
            #pragma unroll
            for (int nt = 0; nt < 8; nt++){
                int col = (wc*8 + nt)*8 + tg*2;
                float b0 = sBias[col], b1 = sBias[col+1];
                float c0 = fmaxf(acc[mt][nt][0] + b0, 0.f);
                float c1 = fmaxf(acc[mt][nt][1] + b1, 0.f);
                float c2 = fmaxf(acc[mt][nt][2] + b0, 0.f);
                float c3 = fmaxf(acc[mt][nt][3] + b1, 0.f);
                if (r0 < nrows){
                    *(float2*)(C + (size_t)r0*HIDN + col) = make_float2(c0,c1);
                    Cb[(size_t)r0*64 + (col >> 1)] = bf2_rn(c0,c1);
                }
                if (r1 < nrows){
                    *(float2*)(C + (size_t)r1*HIDN + col) = make_float2(c2,c3);
                    Cb[(size_t)r1*64 + (col >> 1)] = bf2_rn(c2,c3);
                }
            }
        }
    }
}

// ---- SAGE GEMM: column-split, 64 cols per CTA, 2 CTAs/SM; optional bf16 mirror ----
__global__ void __launch_bounds__(256, 2)
mgemm_sage(const float* __restrict__ A1, const float* __restrict__ A2,
           const float* __restrict__ W1, const float* __restrict__ W2,
           const float* __restrict__ bias, float* __restrict__ C,
           uint32_t* __restrict__ Cb, int nrows, int relu)
{
    const int WSP = 16*8*32*8;    // 32768 bytes per split (16 chunks x 8 n-tiles)

    extern __shared__ uint8_t smem[];
    float*   sBias = (float*)smem;
    uint8_t* sW    = smem + 512;

    int tid  = threadIdx.x;
    int w    = tid >> 5, lane = tid & 31;
    int wr   = w & 3,    wc   = w >> 2;
    int g    = lane >> 2, tg  = lane & 3;
    int half   = (int)(blockIdx.x & 1);
    int bstart = (int)(blockIdx.x >> 1);
    int bstep  = (int)(gridDim.x >> 1);

    for (int idx = tid; idx < 16*8*32; idx += 256){
        int l   = idx & 31;
        int t   = idx >> 5;
        int ntl = t & 7;
        int c   = t >> 3;
        int gg  = l >> 2, tt = l & 3;
        int n   = (half*8 + ntl)*8 + gg;
        int kg  = c*16 + tt*2;
        float wv[4];
        #pragma unroll
        for (int q = 0; q < 4; q++){
            int k = kg + ((q & 1) ? 1 : 0) + ((q >> 1) ? 8 : 0);
            wv[q] = (k < 128) ? W1[(size_t)k*128 + n] : W2[(size_t)(k-128)*128 + n];
        }
        uint32_t slot = (uint32_t)idx * 8u;
        *(uint2*)(sW + slot)       = make_uint2(pack_hi2(wv[0],wv[1]), pack_hi2(wv[2],wv[3]));
        *(uint2*)(sW + WSP + slot) = make_uint2(pack_lo2(wv[0],wv[1]), pack_lo2(wv[2],wv[3]));
    }
    for (int i = tid; i < 128; i += 256) sBias[i] = bias[i];
    __syncthreads();

    int ntiles = (nrows + 127) >> 7;
    for (int tile = bstart; tile < ntiles; tile += bstep){
        int rowbase = tile << 7;
        float acc[2][4][4];
        #pragma unroll
        for (int i = 0; i < 2; i++)
            #pragma unroll
            for (int j = 0; j < 4; j++)
                #pragma unroll
                for (int q = 0; q < 4; q++) acc[i][j][q] = 0.f;

        gpass<MPLAIN, 128, 8, 16*8*32*8, 8, 4>(A1, nullptr, nullptr, nullptr, nullptr, sW, 0,
                                               rowbase, nrows, wr, wc, lane, acc);
        gpass<MPLAIN, 128, 8, 16*8*32*8, 8, 4>(A2, nullptr, nullptr, nullptr, nullptr, sW, 8,
                                               rowbase, nrows, wr, wc, lane, acc);

        #pragma unroll
        for (int mt = 0; mt < 2; mt++){
            int r0 = rowbase + wr*32 + mt*16 + g;
            int r1 = r0 + 8;
            #pragma unroll
            for (int nt = 0; nt < 4; nt++){
                int col = (half*8 + wc*4 + nt)*8 + tg*2;
                float b0 = sBias[col], b1 = sBias[col+1];
                float c0 = acc[mt][nt][0] + b0, c1 = acc[mt][nt][1] + b1;
                float c2 = acc[mt][nt][2] + b0, c3 = acc[mt][nt][3] + b1;
                if (relu){
                    c0 = fmaxf(c0,0.f); c1 = fmaxf(c1,0.f);
                    c2 = fmaxf(c2,0.f); c3 = fmaxf(c3,0.f);
                }
                if (r0 < nrows){
                    *(float2*)(C + (size_t)r0*HIDN + col) = make_float2(c0,c1);
                    if (Cb) Cb[(size_t)r0*64 + (col >> 1)] = bf2_rn(c0,c1);
                }
                if (r1 < nrows){
                    *(float2*)(C + (size_t)r1*HIDN + col) = make_float2(c2,c3);
                    if (Cb) Cb[(size_t)r1*64 + (col >> 1)] = bf2_rn(c2,c3);
                }
            }
        }
    }
}

// ---------------- launch ----------------
extern "C" void kernel_launch(void* const* d_in, const int* in_sizes, int n_in,
                              void* d_out, int out_size){
    const float* x_pol  = (const float*)d_in[0];
    const int*   psidx  = (const int*)  d_in[1];
    const float* x_comp = (const float*)d_in[2];
    const int*   csct   = (const int*)  d_in[3];
    const int*   cind   = (const int*)  d_in[4];
    const int*   eidx   = (const int*)  d_in[5];
    const float* semb   = (const float*)d_in[6];
    const float* scemb  = (const float*)d_in[7];
    const float* iemb   = (const float*)d_in[8];
    const float* W_pol  = (const float*)d_in[9];
    const float* b_pol  = (const float*)d_in[10];
    const float* W_comp = (const float*)d_in[11];
    const float* b_comp = (const float*)d_in[12];
    const float* Wl1    = (const float*)d_in[13];
    const float* bl1    = (const float*)d_in[14];
    const float* Wr1    = (const float*)d_in[15];
    const float* Wl2    = (const float*)d_in[16];
    const float* bl2    = (const float*)d_in[17];
    const float* Wr2    = (const float*)d_in[18];
    float* out = (float*)d_out;

    int NP = in_sizes[0]/64;
    int NC = in_sizes[2]/96;
    int E  = in_sizes[5]/2;
    int N  = NP + NC;
    const int* srcv = eidx;
    const int* dstv = eidx + E;

    float *hP, *h1P, *mP;
    uint32_t* hbP;
    cudaGetSymbolAddress((void**)&hP,  g_h);
    cudaGetSymbolAddress((void**)&h1P, g_h1);
    cudaGetSymbolAddress((void**)&mP,  g_m);
    cudaGetSymbolAddress((void**)&hbP, g_hb);

    const int SM_POL  = 512 + 2*( 5*16*32*8);   //  41,472
    const int SM_COMP = 512 + 2*( 7*16*32*8);   //  57,856
    const int SM_SAGE = 512 + 2*(16* 8*32*8);   //  66,048
    cudaFuncSetAttribute(mgemm_enc< 72, 5, MPOL >, cudaFuncAttributeMaxDynamicSharedMemorySize, SM_POL);
    cudaFuncSetAttribute(mgemm_enc<112, 7, MCOMP>, cudaFuncAttributeMaxDynamicSharedMemorySize, SM_COMP);
    cudaFuncSetAttribute(mgemm_sage,               cudaFuncAttributeMaxDynamicSharedMemorySize, SM_SAGE);

    static cudaStream_t s2 = nullptr;
    static cudaEvent_t  ev_fork = nullptr, ev_h = nullptr, ev_m1 = nullptr,
                        ev_h1 = nullptr, ev_m2 = nullptr;
    if (!s2){
        cudaStreamCreateWithFlags(&s2, cudaStreamNonBlocking);
        cudaEventCreateWithFlags(&ev_fork, cudaEventDisableTiming);
        cudaEventCreateWithFlags(&ev_h,    cudaEventDisableTiming);
        cudaEventCreateWithFlags(&ev_m1,   cudaEventDisableTiming);
        cudaEventCreateWithFlags(&ev_h1,   cudaEventDisableTiming);
        cudaEventCreateWithFlags(&ev_m2,   cudaEventDisableTiming);
    }

    cudaEventRecord(ev_fork, 0);
    cudaStreamWaitEvent(s2, ev_fork, 0);

    // ---- side stream s2: CSR build (concurrent with encoders) ----
    int NB = (N + 1023) / 1024;
    zero_deg   <<<NB, 1024, 0, s2>>>(N);
    count_deg  <<<2048, 256, 0, s2>>>(dstv, E);
    scan_blocks<<<NB, 1024, 0, s2>>>(N);
    scan_bsums <<<1, 256,   0, s2>>>(NB, N, E);
    add_bsums  <<<NB, 1024, 0, s2>>>(N);
    fill_csr   <<<2048, 256, 0, s2>>>(srcv, dstv, E);

    // ---- main: encoders (emit fp32 h + bf16 mirror) ----
    mgemm_enc< 72, 5, MPOL ><<<148, 256, SM_POL>>>(
        x_pol, psidx, nullptr, semb, nullptr, W_pol, b_pol, hP, hbP, NP);
    mgemm_enc<112, 7, MCOMP><<<148, 256, SM_COMP>>>(
        x_comp, csct, cind, scemb, iemb, W_comp, b_comp,
        hP + (size_t)NP*HIDN, hbP + (size_t)NP*64, NC);
    cudaEventRecord(ev_h, 0);

    // ---- layer 1 ----
    cudaStreamWaitEvent(s2, ev_h, 0);
    agg_mean_bf<<<(N + 7)/8, 256, 0, s2>>>(hbP, mP, N);
    cudaEventRecord(ev_m1, s2);
    cudaStreamWaitEvent(0, ev_m1, 0);
    mgemm_sage<<<296, 256, SM_SAGE>>>(mP, hP, Wl1, Wr1, bl1, h1P, hbP, N, 1);
    cudaEventRecord(ev_h1, 0);

    // ---- layer 2 -> d_out ----
    cudaStreamWaitEvent(s2, ev_h1, 0);
    agg_mean_bf<<<(N + 7)/8, 256, 0, s2>>>(hbP, mP, N);
    cudaEventRecord(ev_m2, s2);
    cudaStreamWaitEvent(0, ev_m2, 0);
    mgemm_sage<<<296, 256, SM_SAGE>>>(mP, h1P, Wl2, Wr2, bl2, out, nullptr, N, 0);
}